// round 1
// baseline (speedup 1.0000x reference)
#include <cuda_runtime.h>
#include <math_constants.h>
#include <climits>
#include <cstdint>

// Problem shape (fixed by setup_inputs)
#define BB 512
#define NN 131072
#define DD 512
#define KK 16

// Scratch (device-global arrays: allocation-free per harness rules)
__device__ float g_sims[(size_t)BB * NN];     // 256 MiB boosted sims
__device__ float g_qnorm[BB];
__device__ float g_mnorm[NN];
__device__ float g_boost[NN];
__device__ int   g_topidx[BB * KK];

// ---------------------------------------------------------------------------
// Row L2 norms: one warp per row of a [nrows, 512] f32 matrix.
// which==0 -> g_qnorm, which==1 -> g_mnorm
// ---------------------------------------------------------------------------
__global__ void row_norms_kernel(const float* __restrict__ X, int nrows, int which) {
    const int warps = blockDim.x >> 5;
    const int row = blockIdx.x * warps + (threadIdx.x >> 5);
    const int lane = threadIdx.x & 31;
    if (row >= nrows) return;
    const float* x = X + (size_t)row * DD;
    float s = 0.0f;
#pragma unroll
    for (int d = 0; d < DD / 32; ++d) {
        float v = x[d * 32 + lane];
        s = fmaf(v, v, s);
    }
#pragma unroll
    for (int o = 16; o > 0; o >>= 1) s += __shfl_xor_sync(0xffffffffu, s, o);
    if (lane == 0) {
        float r = sqrtf(s);
        if (which == 0) g_qnorm[row] = r;
        else            g_mnorm[row] = r;
    }
}

// ---------------------------------------------------------------------------
// boost[n] = 1 + 0.3 * importance[n]
// ---------------------------------------------------------------------------
__global__ void boost_kernel(const float* __restrict__ imp) {
    int i = blockIdx.x * blockDim.x + threadIdx.x;
    if (i < NN) g_boost[i] = 1.0f + 0.3f * imp[i];
}

// ---------------------------------------------------------------------------
// SGEMM (NT): sims[b][n] = (dot(Q[b], M[n]) / max(qn*mn, eps)) * boost[n]
// Tile 128x128x8, 256 threads, 8x8 micro-tile, smem double-buffered.
// grid = (B/128, N/128)
// ---------------------------------------------------------------------------
__global__ __launch_bounds__(256, 2)
void gemm_sims_kernel(const float* __restrict__ Q, const float* __restrict__ M) {
    __shared__ float As[2][8][128];
    __shared__ float Bs[2][8][128];

    const int tid = threadIdx.x;
    const int b0 = blockIdx.x * 128;
    const int n0 = blockIdx.y * 128;

    const int lrow = tid >> 1;        // 0..127
    const int lcol = (tid & 1) << 2;  // 0 or 4

    const float* qptr = Q + (size_t)(b0 + lrow) * DD + lcol;
    const float* mptr = M + (size_t)(n0 + lrow) * DD + lcol;

    float4 aR = *(const float4*)qptr;
    float4 bR = *(const float4*)mptr;
    As[0][lcol + 0][lrow] = aR.x; As[0][lcol + 1][lrow] = aR.y;
    As[0][lcol + 2][lrow] = aR.z; As[0][lcol + 3][lrow] = aR.w;
    Bs[0][lcol + 0][lrow] = bR.x; Bs[0][lcol + 1][lrow] = bR.y;
    Bs[0][lcol + 2][lrow] = bR.z; Bs[0][lcol + 3][lrow] = bR.w;
    __syncthreads();

    const int tx = tid & 15;   // n direction
    const int ty = tid >> 4;   // b direction

    float acc[8][8];
#pragma unroll
    for (int i = 0; i < 8; ++i) {
#pragma unroll
        for (int j = 0; j < 8; ++j) acc[i][j] = 0.0f;
    }

    const int NK = DD / 8;  // 64
    for (int kt = 0; kt < NK; ++kt) {
        const int cur = kt & 1;
        if (kt + 1 < NK) {
            aR = *(const float4*)(qptr + (kt + 1) * 8);
            bR = *(const float4*)(mptr + (kt + 1) * 8);
        }
#pragma unroll
        for (int k = 0; k < 8; ++k) {
            float a[8], b[8];
            *(float4*)&a[0] = *(const float4*)&As[cur][k][ty * 8];
            *(float4*)&a[4] = *(const float4*)&As[cur][k][ty * 8 + 4];
            *(float4*)&b[0] = *(const float4*)&Bs[cur][k][tx * 8];
            *(float4*)&b[4] = *(const float4*)&Bs[cur][k][tx * 8 + 4];
#pragma unroll
            for (int i = 0; i < 8; ++i) {
#pragma unroll
                for (int j = 0; j < 8; ++j) {
                    acc[i][j] = fmaf(a[i], b[j], acc[i][j]);
                }
            }
        }
        if (kt + 1 < NK) {
            const int nxt = cur ^ 1;
            As[nxt][lcol + 0][lrow] = aR.x; As[nxt][lcol + 1][lrow] = aR.y;
            As[nxt][lcol + 2][lrow] = aR.z; As[nxt][lcol + 3][lrow] = aR.w;
            Bs[nxt][lcol + 0][lrow] = bR.x; Bs[nxt][lcol + 1][lrow] = bR.y;
            Bs[nxt][lcol + 2][lrow] = bR.z; Bs[nxt][lcol + 3][lrow] = bR.w;
            __syncthreads();
        }
    }

    // Epilogue: exact reference op order: (dot / max(qn*mn, eps)) * boost
    float mn[8], bst[8];
#pragma unroll
    for (int j = 0; j < 8; ++j) {
        int n = n0 + tx * 8 + j;
        mn[j]  = g_mnorm[n];
        bst[j] = g_boost[n];
    }
#pragma unroll
    for (int i = 0; i < 8; ++i) {
        int b = b0 + ty * 8 + i;
        float qn = g_qnorm[b];
        float outv[8];
#pragma unroll
        for (int j = 0; j < 8; ++j) {
            float denom = fmaxf(qn * mn[j], 1e-8f);
            outv[j] = (acc[i][j] / denom) * bst[j];
        }
        float* dst = g_sims + (size_t)b * NN + (size_t)(n0 + tx * 8);
        *(float4*)dst       = *(const float4*)&outv[0];
        *(float4*)(dst + 4) = *(const float4*)&outv[4];
    }
}

// ---------------------------------------------------------------------------
// Top-16 per query with jax.lax.top_k semantics (val desc, ties -> lowest idx).
// One block (256 threads) per query. Each thread keeps a sorted register
// top-16 over its strided slice, then 16 rounds of block argmax selection.
// ---------------------------------------------------------------------------
__global__ void topk_kernel(float* __restrict__ outvals) {
    const int b = blockIdx.x;
    const int t = threadIdx.x;
    const float* row = g_sims + (size_t)b * NN;

    float v[KK];
    int   ix[KK];
#pragma unroll
    for (int i = 0; i < KK; ++i) { v[i] = -CUDART_INF_F; ix[i] = INT_MAX; }

    // Strided scan; encounter order is ascending index within a thread, so a
    // strict '>' bubble keeps stable (lowest-index-first) tie ordering.
    for (int n = t; n < NN; n += 256) {
        float x = row[n];
        if (x > v[KK - 1]) {
            v[KK - 1] = x; ix[KK - 1] = n;
#pragma unroll
            for (int p = KK - 1; p >= 1; --p) {
                if (v[p] > v[p - 1]) {
                    float tv = v[p]; v[p] = v[p - 1]; v[p - 1] = tv;
                    int   ti = ix[p]; ix[p] = ix[p - 1]; ix[p - 1] = ti;
                }
            }
        }
    }

    __shared__ float rv[256];
    __shared__ int   ri[256];

    float* ov = outvals + b * KK;
    for (int round = 0; round < KK; ++round) {
        // local best among this thread's surviving entries
        float bvv = -CUDART_INF_F; int bii = INT_MAX;
#pragma unroll
        for (int j = 0; j < KK; ++j) {
            bool better = (v[j] > bvv) || (v[j] == bvv && ix[j] < bii);
            if (better) { bvv = v[j]; bii = ix[j]; }
        }
        rv[t] = bvv; ri[t] = bii;
        __syncthreads();
        for (int s = 128; s > 0; s >>= 1) {
            if (t < s) {
                float ov2 = rv[t + s]; int oi2 = ri[t + s];
                if (ov2 > rv[t] || (ov2 == rv[t] && oi2 < ri[t])) {
                    rv[t] = ov2; ri[t] = oi2;
                }
            }
            __syncthreads();
        }
        float wv = rv[0];
        int   wi = ri[0];
        if (t == 0) {
            ov[round] = wv;
            g_topidx[b * KK + round] = wi;
        }
        // remove the winner from whoever owns it
#pragma unroll
        for (int j = 0; j < KK; ++j) {
            if (ix[j] == wi) { v[j] = -CUDART_INF_F; ix[j] = INT_MAX; }
        }
        __syncthreads();
    }
}

// ---------------------------------------------------------------------------
// Gather: out[B*K + (b*K+j)*D ...] = memory_matrix[topidx[b][j]]
// grid = (K, B), 128 threads, one float4 per thread.
// ---------------------------------------------------------------------------
__global__ void gather_kernel(const float* __restrict__ M, float* __restrict__ out) {
    const int j = blockIdx.x;
    const int b = blockIdx.y;
    const int idx = g_topidx[b * KK + j];
    const float4* src = (const float4*)(M + (size_t)idx * DD);
    float4* dst = (float4*)(out + (size_t)BB * KK + ((size_t)(b * KK + j)) * DD);
    dst[threadIdx.x] = src[threadIdx.x];
}

// ---------------------------------------------------------------------------
// Launch
// ---------------------------------------------------------------------------
extern "C" void kernel_launch(void* const* d_in, const int* in_sizes, int n_in,
                              void* d_out, int out_size) {
    const float* Q   = (const float*)d_in[0];   // [512, 512]
    const float* M   = (const float*)d_in[1];   // [131072, 512]
    const float* imp = (const float*)d_in[2];   // [131072]
    float* out = (float*)d_out;                 // vals [512,16] ++ gathered [512,16,512]

    // norms + boost
    row_norms_kernel<<<BB / 8, 256>>>(Q, BB, 0);
    row_norms_kernel<<<NN / 8, 256>>>(M, NN, 1);
    boost_kernel<<<NN / 256, 256>>>(imp);

    // boosted cosine similarity matrix
    dim3 ggrid(BB / 128, NN / 128);  // (4, 1024)
    gemm_sims_kernel<<<ggrid, 256>>>(Q, M);

    // top-k values (written directly to out) + indices
    topk_kernel<<<BB, 256>>>(out);

    // gather memory rows
    dim3 grid_g(KK, BB);
    gather_kernel<<<grid_g, 128>>>(M, out);
}

// round 3
// speedup vs baseline: 1.9106x; 1.9106x over previous
#include <cuda_runtime.h>
#include <cuda_bf16.h>
#include <math_constants.h>
#include <climits>
#include <cstdint>

// Problem shape (fixed by setup_inputs)
#define BB 512
#define NN 131072
#define DD 512
#define KK 16

#define CAND_CAP 1024
#define MARGIN 0.01f

// ---------------------------------------------------------------------------
// Device-global scratch (allocation-free)
// ---------------------------------------------------------------------------
__device__ float          g_sims[(size_t)BB * NN];      // 256 MiB approx boosted sims
__device__ __nv_bfloat16  g_mbf[(size_t)NN * DD];       // 128 MiB bf16 memory
__device__ __nv_bfloat16  g_qbf[(size_t)BB * DD];       // bf16 queries
__device__ float g_qrs[BB];       // 1 / ||q_b||
__device__ float g_nb[NN];        // (1 + 0.3*imp[n]) / ||m_n||
__device__ int   g_cand[(size_t)BB * CAND_CAP];
__device__ int   g_candcnt[BB];
__device__ int   g_topidx[BB * KK];

__device__ __forceinline__ uint32_t smem_u32(const void* p) {
    uint32_t a;
    asm("{ .reg .u64 t; cvta.to.shared.u64 t, %1; cvt.u32.u64 %0, t; }" : "=r"(a) : "l"(p));
    return a;
}

__device__ __forceinline__ void ldmatrix_x4(uint32_t& r0, uint32_t& r1, uint32_t& r2, uint32_t& r3,
                                            uint32_t addr) {
    asm volatile("ldmatrix.sync.aligned.m8n8.x4.shared.b16 {%0,%1,%2,%3}, [%4];"
                 : "=r"(r0), "=r"(r1), "=r"(r2), "=r"(r3) : "r"(addr));
}

__device__ __forceinline__ void mma_bf16(float* c, const uint32_t* a, const uint32_t* b) {
    asm volatile(
        "mma.sync.aligned.m16n8k16.row.col.f32.bf16.bf16.f32 "
        "{%0,%1,%2,%3}, {%4,%5,%6,%7}, {%8,%9}, {%0,%1,%2,%3};"
        : "+f"(c[0]), "+f"(c[1]), "+f"(c[2]), "+f"(c[3])
        : "r"(a[0]), "r"(a[1]), "r"(a[2]), "r"(a[3]), "r"(b[0]), "r"(b[1]));
}

// ---------------------------------------------------------------------------
// Fused: bf16 conversion + scale precompute (one read of X). Warp per row.
// mode 0 (queries):  scale[row] = 1/||x||
// mode 1 (memory):   scale[row] = (1 + 0.3*imp[row]) / ||x||
// ---------------------------------------------------------------------------
__global__ void conv_norm_kernel(const float* __restrict__ X, __nv_bfloat16* __restrict__ Xb,
                                 float* __restrict__ scale, const float* __restrict__ imp,
                                 int nrows, int mode) {
    const int row  = blockIdx.x * 8 + (threadIdx.x >> 5);
    const int lane = threadIdx.x & 31;
    if (row >= nrows) return;
    const float4* src = (const float4*)(X + (size_t)row * DD);
    float s = 0.0f;
#pragma unroll
    for (int i = 0; i < 4; ++i) {
        float4 f = src[i * 32 + lane];
        s += f.x * f.x + f.y * f.y + f.z * f.z + f.w * f.w;
        __nv_bfloat162 p0 = __floats2bfloat162_rn(f.x, f.y);
        __nv_bfloat162 p1 = __floats2bfloat162_rn(f.z, f.w);
        uint2 u;
        u.x = *(uint32_t*)&p0;
        u.y = *(uint32_t*)&p1;
        *(uint2*)(Xb + (size_t)row * DD + (size_t)(i * 32 + lane) * 4) = u;
    }
#pragma unroll
    for (int o = 16; o > 0; o >>= 1) s += __shfl_xor_sync(0xffffffffu, s, o);
    if (lane == 0) {
        float nrm = sqrtf(s);
        if (mode == 0) scale[row] = 1.0f / nrm;
        else           scale[row] = (1.0f + 0.3f * imp[row]) / nrm;
    }
}

// ---------------------------------------------------------------------------
// bf16 HMMA GEMM (NT): sims[b][n] = dot(Qbf[b], Mbf[n]) * qrs[b] * nb[n]
// CTA tile 128x128, 8 warps in 4(M)x2(N), warp tile 32x64, K-block 32,
// double-buffered static smem (rows padded to 40 bf16 for ldmatrix).
// grid = (B/128, N/128) = (4, 1024); x fast-varying so the 4 CTAs sharing an
// M-tile run together (L2 reuse of g_mbf).
// ---------------------------------------------------------------------------
#define KBLK 32
#define NKB  (DD / KBLK)   // 16
#define APAD 40

__global__ __launch_bounds__(256)
void gemm_bf16_kernel() {
    __shared__ __align__(16) __nv_bfloat16 As[2][128][APAD];
    __shared__ __align__(16) __nv_bfloat16 Bs[2][128][APAD];

    const int tid  = threadIdx.x;
    const int warp = tid >> 5;
    const int lane = tid & 31;
    const int wm = warp & 3;   // M position (0..3) -> rows wm*32
    const int wn = warp >> 2;  // N position (0..1) -> cols wn*64

    const int b0 = blockIdx.x * 128;
    const int n0 = blockIdx.y * 128;

    const __nv_bfloat16* Abase = g_qbf + (size_t)b0 * DD;
    const __nv_bfloat16* Bbase = g_mbf + (size_t)n0 * DD;

    // global load lane mapping: 512 16B-chunks per tile, 2 per thread
    const int grow = tid >> 2;        // 0..63
    const int gcol = (tid & 3) * 8;   // element offset of the 16B chunk

    float acc[2][8][4];
#pragma unroll
    for (int mt = 0; mt < 2; ++mt)
#pragma unroll
        for (int nt = 0; nt < 8; ++nt)
#pragma unroll
            for (int r = 0; r < 4; ++r) acc[mt][nt][r] = 0.0f;

    // preload kt=0 into buffer 0
    {
        uint4 a0 = *(const uint4*)(Abase + (size_t)grow * DD + gcol);
        uint4 a1 = *(const uint4*)(Abase + (size_t)(grow + 64) * DD + gcol);
        uint4 bq0 = *(const uint4*)(Bbase + (size_t)grow * DD + gcol);
        uint4 bq1 = *(const uint4*)(Bbase + (size_t)(grow + 64) * DD + gcol);
        *(uint4*)&As[0][grow][gcol]      = a0;
        *(uint4*)&As[0][grow + 64][gcol] = a1;
        *(uint4*)&Bs[0][grow][gcol]      = bq0;
        *(uint4*)&Bs[0][grow + 64][gcol] = bq1;
    }
    __syncthreads();

    const uint32_t sA = smem_u32(&As[0][0][0]);
    const uint32_t sB = smem_u32(&Bs[0][0][0]);
    const uint32_t bufstride = 128 * APAD * 2;  // bytes per buffer

    for (int kt = 0; kt < NKB; ++kt) {
        const int cur = kt & 1;
        uint4 a0, a1, bq0, bq1;
        if (kt + 1 < NKB) {
            const int koff = (kt + 1) * KBLK + gcol;
            a0  = *(const uint4*)(Abase + (size_t)grow * DD + koff);
            a1  = *(const uint4*)(Abase + (size_t)(grow + 64) * DD + koff);
            bq0 = *(const uint4*)(Bbase + (size_t)grow * DD + koff);
            bq1 = *(const uint4*)(Bbase + (size_t)(grow + 64) * DD + koff);
        }

        // compute on buffer cur (two k16 steps)
#pragma unroll
        for (int ks = 0; ks < 2; ++ks) {
            const int col = ks * 16 + (lane >> 4) * 8;   // element col within KBLK
            const int rbase = lane & 15;
            uint32_t af[2][4];
#pragma unroll
            for (int mt = 0; mt < 2; ++mt) {
                int row = wm * 32 + mt * 16 + rbase;
                uint32_t addr = sA + (uint32_t)cur * bufstride + (uint32_t)(row * APAD + col) * 2;
                ldmatrix_x4(af[mt][0], af[mt][1], af[mt][2], af[mt][3], addr);
            }
            uint32_t bf[8][2];
#pragma unroll
            for (int ng = 0; ng < 4; ++ng) {
                int row = wn * 64 + ng * 16 + rbase;
                uint32_t addr = sB + (uint32_t)cur * bufstride + (uint32_t)(row * APAD + col) * 2;
                uint32_t r0, r1, r2, r3;
                ldmatrix_x4(r0, r1, r2, r3, addr);
                bf[ng * 2 + 0][0] = r0; bf[ng * 2 + 0][1] = r2;
                bf[ng * 2 + 1][0] = r1; bf[ng * 2 + 1][1] = r3;
            }
#pragma unroll
            for (int mt = 0; mt < 2; ++mt)
#pragma unroll
                for (int nt = 0; nt < 8; ++nt)
                    mma_bf16(acc[mt][nt], af[mt], bf[nt]);
        }

        if (kt + 1 < NKB) {
            const int nxt = cur ^ 1;
            __syncthreads();  // everyone done reading buffer nxt (iteration kt-1)
            *(uint4*)&As[nxt][grow][gcol]      = a0;
            *(uint4*)&As[nxt][grow + 64][gcol] = a1;
            *(uint4*)&Bs[nxt][grow][gcol]      = bq0;
            *(uint4*)&Bs[nxt][grow + 64][gcol] = bq1;
            __syncthreads();
        }
    }

    // Epilogue: sims = dot * qrs[b] * nb[n]; float2 stores
    const int r0 = lane >> 2;          // 0..7
    const int c0 = (lane & 3) * 2;     // 0,2,4,6
#pragma unroll
    for (int mt = 0; mt < 2; ++mt) {
        const int brow0 = b0 + wm * 32 + mt * 16 + r0;
        const float q0 = g_qrs[brow0];
        const float q1 = g_qrs[brow0 + 8];
        float* row0p = g_sims + (size_t)brow0 * NN;
        float* row1p = g_sims + (size_t)(brow0 + 8) * NN;
#pragma unroll
        for (int nt = 0; nt < 8; ++nt) {
            const int n = n0 + wn * 64 + nt * 8 + c0;
            const float nb0 = g_nb[n];
            const float nb1 = g_nb[n + 1];
            float2 v0, v1;
            v0.x = acc[mt][nt][0] * q0 * nb0;
            v0.y = acc[mt][nt][1] * q0 * nb1;
            v1.x = acc[mt][nt][2] * q1 * nb0;
            v1.y = acc[mt][nt][3] * q1 * nb1;
            *(float2*)(row0p + n) = v0;
            *(float2*)(row1p + n) = v1;
        }
    }
}

// ---------------------------------------------------------------------------
// Candidate selection: per query, approx v16 via 16-round block argmax over
// per-thread top-16 lists, then dump all list entries >= v16 - MARGIN.
// ---------------------------------------------------------------------------
__global__ void select_kernel() {
    const int b = blockIdx.x;
    const int t = threadIdx.x;
    const float* row = g_sims + (size_t)b * NN;

    float v[KK];  int ix[KK];
    float v2[KK]; int ix2[KK];
#pragma unroll
    for (int i = 0; i < KK; ++i) { v[i] = -CUDART_INF_F; ix[i] = INT_MAX; }

    for (int n = t; n < NN; n += 256) {
        float x = row[n];
        if (x > v[KK - 1]) {
            v[KK - 1] = x; ix[KK - 1] = n;
#pragma unroll
            for (int p = KK - 1; p >= 1; --p) {
                if (v[p] > v[p - 1]) {
                    float tv = v[p]; v[p] = v[p - 1]; v[p - 1] = tv;
                    int   ti = ix[p]; ix[p] = ix[p - 1]; ix[p - 1] = ti;
                }
            }
        }
    }
#pragma unroll
    for (int i = 0; i < KK; ++i) { v2[i] = v[i]; ix2[i] = ix[i]; }

    __shared__ float rv[256];
    __shared__ int   ri[256];
    __shared__ float s_v16;
    __shared__ int   s_cnt;

    for (int round = 0; round < KK; ++round) {
        float bvv = -CUDART_INF_F; int bii = INT_MAX;
#pragma unroll
        for (int j = 0; j < KK; ++j) {
            bool better = (v[j] > bvv) || (v[j] == bvv && ix[j] < bii);
            if (better) { bvv = v[j]; bii = ix[j]; }
        }
        rv[t] = bvv; ri[t] = bii;
        __syncthreads();
        for (int s = 128; s > 0; s >>= 1) {
            if (t < s) {
                float ov2 = rv[t + s]; int oi2 = ri[t + s];
                if (ov2 > rv[t] || (ov2 == rv[t] && oi2 < ri[t])) { rv[t] = ov2; ri[t] = oi2; }
            }
            __syncthreads();
        }
        if (round == KK - 1 && t == 0) s_v16 = rv[0];
        int wi = ri[0];
#pragma unroll
        for (int j = 0; j < KK; ++j) {
            if (ix[j] == wi) { v[j] = -CUDART_INF_F; ix[j] = INT_MAX; }
        }
        __syncthreads();
    }

    if (t == 0) s_cnt = 0;
    __syncthreads();
    const float thresh = s_v16 - MARGIN;
#pragma unroll
    for (int j = 0; j < KK; ++j) {
        if (v2[j] >= thresh) {
            int slot = atomicAdd(&s_cnt, 1);
            if (slot < CAND_CAP) g_cand[(size_t)b * CAND_CAP + slot] = ix2[j];
        }
    }
    __syncthreads();
    if (t == 0) g_candcnt[b] = min(s_cnt, CAND_CAP);
}

// ---------------------------------------------------------------------------
// Exact rescore in double + stable top-16 (val desc, idx asc).
// ---------------------------------------------------------------------------
__global__ void rescore_kernel(const float* __restrict__ Q, const float* __restrict__ M,
                               const float* __restrict__ imp, float* __restrict__ out) {
    const int b = blockIdx.x;
    const int t = threadIdx.x;
    const int w = t >> 5;
    const int lane = t & 31;
    const int cnt = g_candcnt[b];

    __shared__ double s_val[CAND_CAP];
    __shared__ int    s_idx[CAND_CAP];

    const float* q = Q + (size_t)b * DD;
    double q2 = 0.0;
    for (int d = lane; d < DD; d += 32) { double x = q[d]; q2 += x * x; }
#pragma unroll
    for (int o = 16; o > 0; o >>= 1) q2 += __shfl_xor_sync(0xffffffffu, q2, o);
    const double qn = sqrt(q2);

    for (int s = w; s < cnt; s += 8) {
        const int idx = g_cand[(size_t)b * CAND_CAP + s];
        const float* m = M + (size_t)idx * DD;
        double dot = 0.0, m2 = 0.0;
        for (int d = lane; d < DD; d += 32) {
            double a = q[d], bb = m[d];
            dot += a * bb;
            m2  += bb * bb;
        }
#pragma unroll
        for (int o = 16; o > 0; o >>= 1) {
            dot += __shfl_xor_sync(0xffffffffu, dot, o);
            m2  += __shfl_xor_sync(0xffffffffu, m2, o);
        }
        if (lane == 0) {
            double den = fmax(qn * sqrt(m2), 1e-8);
            s_val[s] = (dot / den) * (1.0 + 0.3 * (double)imp[idx]);
            s_idx[s] = idx;
        }
    }
    __syncthreads();

    if (t == 0) {
        double bv[KK]; int bi[KK];
#pragma unroll
        for (int i = 0; i < KK; ++i) { bv[i] = -CUDART_INF; bi[i] = INT_MAX; }
        for (int s = 0; s < cnt; ++s) {
            double val = s_val[s]; int id = s_idx[s];
            if (val > bv[KK - 1] || (val == bv[KK - 1] && id < bi[KK - 1])) {
                bv[KK - 1] = val; bi[KK - 1] = id;
                for (int p = KK - 1; p >= 1; --p) {
                    bool sw = (bv[p] > bv[p - 1]) || (bv[p] == bv[p - 1] && bi[p] < bi[p - 1]);
                    if (!sw) break;
                    double tv = bv[p]; bv[p] = bv[p - 1]; bv[p - 1] = tv;
                    int    ti = bi[p]; bi[p] = bi[p - 1]; bi[p - 1] = ti;
                }
            }
        }
        for (int r = 0; r < KK; ++r) {
            out[b * KK + r] = (float)bv[r];
            g_topidx[b * KK + r] = bi[r];
        }
    }
}

// ---------------------------------------------------------------------------
// Gather memory rows for the final indices.
// ---------------------------------------------------------------------------
__global__ void gather_kernel(const float* __restrict__ M, float* __restrict__ out) {
    const int j = blockIdx.x;
    const int b = blockIdx.y;
    const int idx = g_topidx[b * KK + j];
    const float4* src = (const float4*)(M + (size_t)idx * DD);
    float4* dst = (float4*)(out + (size_t)BB * KK + ((size_t)(b * KK + j)) * DD);
    dst[threadIdx.x] = src[threadIdx.x];
}

// ---------------------------------------------------------------------------
// Launch
// ---------------------------------------------------------------------------
extern "C" void kernel_launch(void* const* d_in, const int* in_sizes, int n_in,
                              void* d_out, int out_size) {
    const float* Q   = (const float*)d_in[0];   // [512, 512]
    const float* M   = (const float*)d_in[1];   // [131072, 512]
    const float* imp = (const float*)d_in[2];   // [131072]
    float* out = (float*)d_out;                 // vals [512,16] ++ gathered [512,16,512]

    __nv_bfloat16 *qbf_ptr, *mbf_ptr;
    float *qrs_ptr, *nb_ptr;
    cudaGetSymbolAddress((void**)&qbf_ptr, g_qbf);
    cudaGetSymbolAddress((void**)&mbf_ptr, g_mbf);
    cudaGetSymbolAddress((void**)&qrs_ptr, g_qrs);
    cudaGetSymbolAddress((void**)&nb_ptr, g_nb);

    conv_norm_kernel<<<BB / 8, 256>>>(Q, qbf_ptr, qrs_ptr, nullptr, BB, 0);
    conv_norm_kernel<<<NN / 8, 256>>>(M, mbf_ptr, nb_ptr, imp, NN, 1);

    dim3 ggrid(BB / 128, NN / 128);   // (4, 1024)
    gemm_bf16_kernel<<<ggrid, 256>>>();

    select_kernel<<<BB, 256>>>();
    rescore_kernel<<<BB, 256>>>(Q, M, imp, out);

    dim3 grid_g(KK, BB);
    gather_kernel<<<grid_g, 128>>>(M, out);
}